// round 15
// baseline (speedup 1.0000x reference)
#include <cuda_runtime.h>
#include <math_constants.h>

// Problem constants
#define BB 64
#define DD 8732
#define CC 21
#define BD (BB*DD)            // 558848
#define NBUCK 65536
#define CHUNKS 1024           // 64 buckets per chunk
#define CMP_T 256
#define CMP_G (BD/CMP_T)      // 2183 exactly (558848 = 2183*256)
#define ROW_FLOATS (CMP_T*CC) // 5376
#define ROW_VEC4 (ROW_FLOATS/4) // 1344

// ---------------- device scratch (no allocation allowed) ----------------
// Zero-initialized at module load. The last block scrubs every global it
// dirtied back to zero before exiting, so each kernel_launch call (correctness
// run, every graph replay) starts from identical clean state. Deterministic.
__device__ float        g_cmp[BD];        // compacted positive candidates
__device__ unsigned int g_hist1[NBUCK];
__device__ unsigned int g_chunk1[CHUNKS];
__device__ float        g_pos_sum;
__device__ unsigned int g_npos;
__device__ unsigned int g_ncand;
__device__ int          g_T1;        // <0 => take every positive candidate
__device__ unsigned int g_need1;
__device__ unsigned int g_cnt1;

// ---------------- level-1 radix select, 256-thread block ----------------
// Writes g_T1 (boundary high-16 bucket, or -1 = take all) and g_need1
// (remaining k within that bucket, in [1, count(T1)]).
__device__ void radix_scan_256(const unsigned int* __restrict__ hist,
                               const unsigned int* __restrict__ chunk,
                               unsigned int k)
{
    __shared__ unsigned int part[256];
    __shared__ unsigned int found[2];
    __shared__ unsigned int suf[128];
    int t = threadIdx.x;
    int base4 = t * 4;
    part[t] = chunk[base4] + chunk[base4 + 1] + chunk[base4 + 2] + chunk[base4 + 3];
    __syncthreads();
    for (int off = 1; off < 256; off <<= 1) {
        unsigned int v = (t + off < 256) ? part[t + off] : 0u;
        __syncthreads();
        part[t] += v;
        __syncthreads();
    }
    unsigned int total = part[0];
    if (k == 0u || total < k) {
        if (t == 0) { g_T1 = -1; g_need1 = 0u; }  // take all positives
        return;
    }
    unsigned int above = (t < 255) ? part[t + 1] : 0u;
    if (part[t] >= k && above < k) {
        unsigned int cum = above;
        for (int cj = 3; cj >= 0; cj--) {
            unsigned int h = chunk[base4 + cj];
            if (cum + h >= k) { found[0] = (unsigned int)(base4 + cj); found[1] = k - cum; break; }
            cum += h;
        }
    }
    __syncthreads();
    unsigned int c = found[0], k2 = found[1];
    if (t < 128) suf[t] = (t < 64) ? hist[c * 64 + t] : 0u;
    __syncthreads();
    for (int off = 1; off < 64; off <<= 1) {
        unsigned int v = (t < 64) ? suf[t + off] : 0u;
        __syncthreads();
        if (t < 64) suf[t] += v;
        __syncthreads();
    }
    if (t < 64) {
        unsigned int ab = suf[t + 1 < 64 ? t + 1 : 64];
        if (suf[t] >= k2 && ab < k2) { g_T1 = (int)(c * 64 + t); g_need1 = k2 - ab; }
    }
}

// 8-bit suffix select over a 256-counter smem histogram.
// On return, fnd[0] = chosen bucket, fnd[1] = remaining k within it.
// h[] is destroyed (turned into inclusive suffix sums). Crossing must exist.
__device__ void suffix_select_256(unsigned int* h, unsigned int k, unsigned int* fnd)
{
    int t = threadIdx.x;
    for (int off = 1; off < 256; off <<= 1) {
        unsigned int v = (t + off < 256) ? h[t + off] : 0u;
        __syncthreads();
        h[t] += v;
        __syncthreads();
    }
    unsigned int above = (t < 255) ? h[t + 1] : 0u;
    if (h[t] >= k && above < k) { fnd[0] = (unsigned int)t; fnd[1] = k - above; }
    __syncthreads();
}

// ---------------- single fused kernel ----------------
__global__ void __launch_bounds__(CMP_T) compute_kernel(
        const float* __restrict__ pred,
        const float* __restrict__ gts,
        const int* __restrict__ pos,   // int32 0/1 (established rounds 3->4)
        float* __restrict__ out)
{
    __shared__ float4 tile4[ROW_VEC4];  // 21504 B; reused as tail scratch later
    float* tile = (float*)tile4;
    int t = threadIdx.x;
    int blk = blockIdx.x;
    int i = blk * CMP_T + t;

    // hoist scattered per-box loads: latency overlaps tile staging + softmax
    int   p_raw = pos[i];
    float gbg   = __ldg(gts + (size_t)i * CC + (CC - 1));  // one-hot bg: 0 or 1

    // coalesced float4 load of this block's 256 rows (blk*21504 B, 16B aligned)
    const float4* src = ((const float4*)pred) + (size_t)blk * ROW_VEC4;
#pragma unroll
    for (int j = 0; j < 5; j++) tile4[t + j * CMP_T] = src[t + j * CMP_T];
    if (t < ROW_VEC4 - 5 * CMP_T) tile4[5 * CMP_T + t] = src[5 * CMP_T + t];
    __syncthreads();

    const float* x = tile + t * CC;   // stride 21: conflict-free (21 coprime 32)
    float xs[CC];
#pragma unroll
    for (int c = 0; c < CC; c++) xs[c] = x[c];

    // 3-way partial trees to break 21-deep dependency chains
    float m0 = xs[0], m1 = xs[1], m2 = xs[2];
#pragma unroll
    for (int c = 3; c < CC; c += 3) {
        m0 = fmaxf(m0, xs[c]);
        if (c + 1 < CC) m1 = fmaxf(m1, xs[c + 1]);
        if (c + 2 < CC) m2 = fmaxf(m2, xs[c + 2]);
    }
    float m = fmaxf(m0, fmaxf(m1, m2));
    float s0 = 0.f, s1 = 0.f, s2 = 0.f;
#pragma unroll
    for (int c = 0; c < CC; c += 3) {
        s0 += __expf(xs[c] - m);
        if (c + 1 < CC) s1 += __expf(xs[c + 1] - m);
        if (c + 2 < CC) s2 += __expf(xs[c + 2] - m);
    }
    float lse = m + __logf(s0 + s1 + s2);

    float my_pos = 0.f;
    unsigned int my_n = 0u;
    float val = 0.f;
    if (p_raw != 0) {
        const float* g = gts + (size_t)i * CC;
        float dot = 0.f;
#pragma unroll
        for (int c = 0; c < CC; c++) dot += g[c] * xs[c];  // one-hot -> x[label]
        my_pos = lse - dot;
        my_n = 1u;
    } else {
        val = gbg * (lse - xs[CC - 1]);                    // >= 0
    }

    // warp-aggregated compaction of positive candidates + level-1 histogram
    unsigned int mask = __ballot_sync(0xffffffffu, val > 0.f);
    if (val > 0.f) {
        int lane = t & 31;
        int leader = __ffs(mask) - 1;
        unsigned int pre = mask & ((1u << lane) - 1u);
        int base;
        if (lane == leader) base = (int)atomicAdd(&g_ncand, (unsigned int)__popc(mask));
        base = __shfl_sync(mask, base, leader);
        g_cmp[base + __popc(pre)] = val;

        unsigned int b = __float_as_uint(val);
        atomicAdd(&g_hist1[b >> 16], 1u);
        atomicAdd(&g_chunk1[b >> 22], 1u);
    }

    // block reduce pos_sum / npos via shuffles
#pragma unroll
    for (int off = 16; off > 0; off >>= 1) {
        my_pos += __shfl_down_sync(0xffffffffu, my_pos, off);
        my_n   += __shfl_down_sync(0xffffffffu, my_n, off);
    }
    __shared__ float wf[8];
    __shared__ unsigned int wi[8];
    if ((t & 31) == 0) { wf[t >> 5] = my_pos; wi[t >> 5] = my_n; }
    __syncthreads();
    if (t < 32) {
        float v = (t < 8) ? wf[t] : 0.f;
        unsigned int n = (t < 8) ? wi[t] : 0u;
#pragma unroll
        for (int off = 4; off > 0; off >>= 1) {
            v += __shfl_down_sync(0xffffffffu, v, off);
            n += __shfl_down_sync(0xffffffffu, n, off);
        }
        if (t == 0) {
            if (v != 0.f) atomicAdd(&g_pos_sum, v);
            if (n != 0u)  atomicAdd(&g_npos, n);
        }
    }

    // ---- last finishing block: level-1 select + full tail + scrub ----
    // Standard fence+counter pattern: every block increments g_cnt1 exactly
    // once; only the final arriver (sees gridDim-1) proceeds. Cannot deadlock.
    __threadfence();
    __shared__ unsigned int isLast;
    if (t == 0) isLast = (atomicAdd(&g_cnt1, 1u) == (unsigned int)gridDim.x - 1u) ? 1u : 0u;
    __syncthreads();
    if (!isLast) return;

    {
        unsigned long long N = (unsigned long long)g_npos;
        unsigned long long k3 = 3ull * N;
        unsigned long long kn = (unsigned long long)BD - N;
        unsigned int k = (unsigned int)(k3 < kn ? k3 : kn);
        radix_scan_256(g_hist1, g_chunk1, k);
    }
    __syncthreads();   // g_T1/g_need1 visible block-wide

    // tail scratch aliased onto the (dead) predicts tile
    unsigned int* sh   = (unsigned int*)tile4;
    unsigned int* h_hi = sh;            // 256 counters (bits 15:8)
    unsigned int* h_lo = sh + 256;      // 256 counters (bits 7:0)
    float*        red  = (float*)(sh + 512);   // 256-float reduce buffer
    float*        keep = (float*)(sh + 768);   // [0]=sum_above
    unsigned int* fnd  = sh + 772;             // select results
    h_hi[t] = 0u; h_lo[t] = 0u;
    __syncthreads();

    int T1 = g_T1;
    unsigned int uT1 = (unsigned int)T1;
    unsigned int need1 = g_need1;
    int nc  = (int)g_ncand;
    int nc4 = nc >> 2;
    int rs  = nc4 << 2;
    const uint4* cmp4 = (const uint4*)g_cmp;

    // ---- pass 1: sum above boundary bucket, mid-8 histogram of bucket, scrub ----
    float acc = 0.f;
    for (int j = t; j < nc4; j += CMP_T) {
        uint4 q = cmp4[j];
        unsigned int bb[4] = {q.x, q.y, q.z, q.w};
#pragma unroll
        for (int e = 0; e < 4; e++) {
            unsigned int b = bb[e];
            unsigned int hi = b >> 16;
            if (T1 < 0 || hi > uT1) acc += __uint_as_float(b);
            else if (hi == uT1) atomicAdd(&h_hi[(b >> 8) & 0xffu], 1u);
            g_hist1[hi] = 0u;          // scrub (threshold-independent)
            g_chunk1[b >> 22] = 0u;
        }
    }
    if (t < nc - rs) {
        unsigned int b = __float_as_uint(g_cmp[rs + t]);
        unsigned int hi = b >> 16;
        if (T1 < 0 || hi > uT1) acc += __uint_as_float(b);
        else if (hi == uT1) atomicAdd(&h_hi[(b >> 8) & 0xffu], 1u);
        g_hist1[hi] = 0u;
        g_chunk1[b >> 22] = 0u;
    }
    red[t] = acc;
    __syncthreads();
    for (int off = 128; off > 0; off >>= 1) {
        if (t < off) red[t] += red[t + off];
        __syncthreads();
    }
    if (t == 0) keep[0] = red[0];
    __syncthreads();

    unsigned int thr_bits = 0u, rem = 0u;
    float sum_in = 0.f;
    if (T1 >= 0) {
        // ---- mid-8 select ----
        suffix_select_256(h_hi, need1, fnd);
        unsigned int c_hi = fnd[0], k2 = fnd[1];

        // ---- pass 2: low-8 histogram of (T1, c_hi) ----
        for (int j = t; j < nc4; j += CMP_T) {
            uint4 q = cmp4[j];
            unsigned int bb[4] = {q.x, q.y, q.z, q.w};
#pragma unroll
            for (int e = 0; e < 4; e++) {
                unsigned int b = bb[e];
                if ((b >> 8) == ((uT1 << 8) | c_hi)) atomicAdd(&h_lo[b & 0xffu], 1u);
            }
        }
        if (t < nc - rs) {
            unsigned int b = __float_as_uint(g_cmp[rs + t]);
            if ((b >> 8) == ((uT1 << 8) | c_hi)) atomicAdd(&h_lo[b & 0xffu], 1u);
        }
        __syncthreads();
        suffix_select_256(h_lo, k2, fnd);
        thr_bits = (uT1 << 16) | (c_hi << 8) | fnd[0];
        rem = fnd[1];

        // ---- pass 3: sum bucket-T1 values strictly above threshold ----
        float a2 = 0.f;
        for (int j = t; j < nc4; j += CMP_T) {
            uint4 q = cmp4[j];
            unsigned int bb[4] = {q.x, q.y, q.z, q.w};
#pragma unroll
            for (int e = 0; e < 4; e++) {
                unsigned int b = bb[e];
                if ((b >> 16) == uT1 && b > thr_bits) a2 += __uint_as_float(b);
            }
        }
        if (t < nc - rs) {
            unsigned int b = __float_as_uint(g_cmp[rs + t]);
            if ((b >> 16) == uT1 && b > thr_bits) a2 += __uint_as_float(b);
        }
        red[t] = a2;
        __syncthreads();
        for (int off = 128; off > 0; off >>= 1) {
            if (t < off) red[t] += red[t + off];
            __syncthreads();
        }
        sum_in = red[0];
    }

    if (t == 0) {
        float neg = keep[0] + sum_in + (float)rem * __uint_as_float(thr_bits);
        out[0] = (g_pos_sum + neg) / (float)g_npos;
    }
    __syncthreads();   // all reads of scalars complete before reset

    if (t == 0) {
        g_pos_sum = 0.f; g_npos = 0u; g_ncand = 0u;
        g_T1 = -1; g_need1 = 0u; g_cnt1 = 0u;
    }
}

extern "C" void kernel_launch(void* const* d_in, const int* in_sizes, int n_in,
                              void* d_out, int out_size) {
    const float* pred = (const float*)d_in[0];
    const float* gts  = (const float*)d_in[1];
    const int*   pos  = (const int*)d_in[2];
    float* out = (float*)d_out;

    compute_kernel<<<CMP_G, CMP_T>>>(pred, gts, pos, out);
}

// round 16
// speedup vs baseline: 1.6894x; 1.6894x over previous
#include <cuda_runtime.h>
#include <math_constants.h>

// Problem constants
#define BB 64
#define DD 8732
#define CC 21
#define BD (BB*DD)            // 558848
#define NBUCK 65536
#define CHUNKS 1024           // 64 buckets per chunk
#define CMP_T 256
#define CMP_G (BD/CMP_T)      // 2183 exactly (558848 = 2183*256)
#define ROW_FLOATS (CMP_T*CC) // 5376
#define ROW_VEC4 (ROW_FLOATS/4) // 1344
#define TT 1024               // tail threads

// ---------------- device scratch (no allocation allowed) ----------------
// Zero-initialized at module load. The pipeline scrubs every global it dirtied
// back to zero each call, so every kernel_launch (correctness run, each graph
// replay) starts from identical clean state. Deterministic.
__device__ float        g_cmp[BD];        // compacted positive candidates
__device__ unsigned int g_hist1[NBUCK];
__device__ unsigned int g_chunk1[CHUNKS];
__device__ float        g_pos_sum;
__device__ unsigned int g_npos;
__device__ unsigned int g_ncand;
__device__ int          g_T1;        // <0 => take every positive candidate
__device__ unsigned int g_need1;
__device__ unsigned int g_cnt1;

// ---------------- level-1 radix select, 256-thread block ----------------
// Writes g_T1 (boundary high-16 bucket, or -1 = take all) and g_need1
// (remaining k within that bucket, in [1, count(T1)]).
__device__ void radix_scan_256(const unsigned int* __restrict__ hist,
                               const unsigned int* __restrict__ chunk,
                               unsigned int k)
{
    __shared__ unsigned int part[256];
    __shared__ unsigned int found[2];
    __shared__ unsigned int suf[128];
    int t = threadIdx.x;
    int base4 = t * 4;
    part[t] = chunk[base4] + chunk[base4 + 1] + chunk[base4 + 2] + chunk[base4 + 3];
    __syncthreads();
    for (int off = 1; off < 256; off <<= 1) {
        unsigned int v = (t + off < 256) ? part[t + off] : 0u;
        __syncthreads();
        part[t] += v;
        __syncthreads();
    }
    unsigned int total = part[0];
    if (k == 0u || total < k) {
        if (t == 0) { g_T1 = -1; g_need1 = 0u; }  // take all positives
        return;
    }
    unsigned int above = (t < 255) ? part[t + 1] : 0u;
    if (part[t] >= k && above < k) {
        unsigned int cum = above;
        for (int cj = 3; cj >= 0; cj--) {
            unsigned int h = chunk[base4 + cj];
            if (cum + h >= k) { found[0] = (unsigned int)(base4 + cj); found[1] = k - cum; break; }
            cum += h;
        }
    }
    __syncthreads();
    unsigned int c = found[0], k2 = found[1];
    if (t < 128) suf[t] = (t < 64) ? hist[c * 64 + t] : 0u;
    __syncthreads();
    for (int off = 1; off < 64; off <<= 1) {
        unsigned int v = (t < 64) ? suf[t + off] : 0u;
        __syncthreads();
        if (t < 64) suf[t] += v;
        __syncthreads();
    }
    if (t < 64) {
        unsigned int ab = suf[t + 1 < 64 ? t + 1 : 64];
        if (suf[t] >= k2 && ab < k2) { g_T1 = (int)(c * 64 + t); g_need1 = k2 - ab; }
    }
}

// ---------------- main compute (identical to the 31.5us R11 version) ----------------
__global__ void __launch_bounds__(CMP_T) compute_kernel(
        const float* __restrict__ pred,
        const float* __restrict__ gts,
        const int* __restrict__ pos)   // int32 0/1 (established rounds 3->4)
{
    __shared__ float4 tile4[ROW_VEC4];  // 21504 B staged predicts tile
    float* tile = (float*)tile4;
    int t = threadIdx.x;
    int blk = blockIdx.x;
    int i = blk * CMP_T + t;

    // hoist scattered per-box loads: latency overlaps tile staging + softmax
    int   p_raw = pos[i];
    float gbg   = __ldg(gts + (size_t)i * CC + (CC - 1));  // one-hot bg: 0 or 1

    // coalesced float4 load of this block's 256 rows (blk*21504 B, 16B aligned)
    const float4* src = ((const float4*)pred) + (size_t)blk * ROW_VEC4;
#pragma unroll
    for (int j = 0; j < 5; j++) tile4[t + j * CMP_T] = src[t + j * CMP_T];
    if (t < ROW_VEC4 - 5 * CMP_T) tile4[5 * CMP_T + t] = src[5 * CMP_T + t];
    __syncthreads();

    const float* x = tile + t * CC;   // stride 21: conflict-free (21 coprime 32)
    float xs[CC];
#pragma unroll
    for (int c = 0; c < CC; c++) xs[c] = x[c];

    // 3-way partial trees to break 21-deep dependency chains
    float m0 = xs[0], m1 = xs[1], m2 = xs[2];
#pragma unroll
    for (int c = 3; c < CC; c += 3) {
        m0 = fmaxf(m0, xs[c]);
        if (c + 1 < CC) m1 = fmaxf(m1, xs[c + 1]);
        if (c + 2 < CC) m2 = fmaxf(m2, xs[c + 2]);
    }
    float m = fmaxf(m0, fmaxf(m1, m2));
    float s0 = 0.f, s1 = 0.f, s2 = 0.f;
#pragma unroll
    for (int c = 0; c < CC; c += 3) {
        s0 += __expf(xs[c] - m);
        if (c + 1 < CC) s1 += __expf(xs[c + 1] - m);
        if (c + 2 < CC) s2 += __expf(xs[c + 2] - m);
    }
    float lse = m + __logf(s0 + s1 + s2);

    float my_pos = 0.f;
    unsigned int my_n = 0u;
    float val = 0.f;
    if (p_raw != 0) {
        const float* g = gts + (size_t)i * CC;
        float dot = 0.f;
#pragma unroll
        for (int c = 0; c < CC; c++) dot += g[c] * xs[c];  // one-hot -> x[label]
        my_pos = lse - dot;
        my_n = 1u;
    } else {
        val = gbg * (lse - xs[CC - 1]);                    // >= 0
    }

    // warp-aggregated compaction of positive candidates + level-1 histogram
    unsigned int mask = __ballot_sync(0xffffffffu, val > 0.f);
    if (val > 0.f) {
        int lane = t & 31;
        int leader = __ffs(mask) - 1;
        unsigned int pre = mask & ((1u << lane) - 1u);
        int base;
        if (lane == leader) base = (int)atomicAdd(&g_ncand, (unsigned int)__popc(mask));
        base = __shfl_sync(mask, base, leader);
        g_cmp[base + __popc(pre)] = val;

        unsigned int b = __float_as_uint(val);
        atomicAdd(&g_hist1[b >> 16], 1u);
        atomicAdd(&g_chunk1[b >> 22], 1u);
    }

    // block reduce pos_sum / npos via shuffles
#pragma unroll
    for (int off = 16; off > 0; off >>= 1) {
        my_pos += __shfl_down_sync(0xffffffffu, my_pos, off);
        my_n   += __shfl_down_sync(0xffffffffu, my_n, off);
    }
    __shared__ float wf[8];
    __shared__ unsigned int wi[8];
    if ((t & 31) == 0) { wf[t >> 5] = my_pos; wi[t >> 5] = my_n; }
    __syncthreads();
    if (t < 32) {
        float v = (t < 8) ? wf[t] : 0.f;
        unsigned int n = (t < 8) ? wi[t] : 0u;
#pragma unroll
        for (int off = 4; off > 0; off >>= 1) {
            v += __shfl_down_sync(0xffffffffu, v, off);
            n += __shfl_down_sync(0xffffffffu, n, off);
        }
        if (t == 0) {
            if (v != 0.f) atomicAdd(&g_pos_sum, v);
            if (n != 0u)  atomicAdd(&g_npos, n);
        }
    }

    // last finishing block runs the level-1 select
    __threadfence();
    __shared__ unsigned int isLast;
    if (t == 0) isLast = (atomicAdd(&g_cnt1, 1u) == (unsigned int)gridDim.x - 1u) ? 1u : 0u;
    __syncthreads();
    if (isLast) {
        unsigned long long N = (unsigned long long)g_npos;
        unsigned long long k3 = 3ull * N;
        unsigned long long kn = (unsigned long long)BD - N;
        unsigned int k = (unsigned int)(k3 < kn ? k3 : kn);
        radix_scan_256(g_hist1, g_chunk1, k);
        if (t == 0) g_cnt1 = 0u;   // reset for next replay (all blocks arrived)
    }
}

// 8-bit suffix select over a 256-counter smem histogram, 1024-thread block.
// h[] destroyed (inclusive suffix sums). Crossing must exist. All threads sync.
__device__ void suffix_select_256w(unsigned int* h, unsigned int k, unsigned int* fnd)
{
    int t = threadIdx.x;
    for (int off = 1; off < 256; off <<= 1) {
        unsigned int v = (t < 256 && t + off < 256) ? h[t + off] : 0u;
        __syncthreads();
        if (t < 256) h[t] += v;
        __syncthreads();
    }
    if (t < 256) {
        unsigned int above = (t < 255) ? h[t + 1] : 0u;
        if (h[t] >= k && above < k) { fnd[0] = (unsigned int)t; fnd[1] = k - above; }
    }
    __syncthreads();
}

// block reduce of 1024 floats -> red32 warp partials -> returns total in ret[0]
__device__ void block_sum_1024(float acc, float* red32, float* ret)
{
    int t = threadIdx.x;
#pragma unroll
    for (int off = 16; off > 0; off >>= 1)
        acc += __shfl_down_sync(0xffffffffu, acc, off);
    if ((t & 31) == 0) red32[t >> 5] = acc;
    __syncthreads();
    if (t < 32) {
        float v = red32[t];
#pragma unroll
        for (int off = 16; off > 0; off >>= 1)
            v += __shfl_down_sync(0xffffffffu, v, off);
        if (t == 0) ret[0] = v;
    }
    __syncthreads();
}

// ---------------- tail: 1024 threads, smem histograms, 3 L2-hot passes + scrub ----
__global__ void __launch_bounds__(TT) tail_kernel(float* __restrict__ out) {
    __shared__ unsigned int h_hi[256];
    __shared__ unsigned int h_lo[256];
    __shared__ float red32[32];
    __shared__ float keep[2];
    __shared__ unsigned int fnd[2];
    int t = threadIdx.x;

    int nc = (int)g_ncand;
    int T1 = g_T1;
    unsigned int uT1 = (unsigned int)T1;
    unsigned int need1 = g_need1;
    int nc4 = nc >> 2;
    int rs  = nc4 << 2;
    const uint4* cmp4 = (const uint4*)g_cmp;

    if (t < 256) { h_hi[t] = 0u; h_lo[t] = 0u; }
    __syncthreads();

    // ---- pass 1: sum above boundary bucket, mid-8 hist of bucket, scrub ----
    float acc = 0.f;
    for (int j = t; j < nc4; j += TT) {
        uint4 q = cmp4[j];
        unsigned int bb[4] = {q.x, q.y, q.z, q.w};
#pragma unroll
        for (int e = 0; e < 4; e++) {
            unsigned int b = bb[e];
            unsigned int hi = b >> 16;
            if (T1 < 0 || hi > uT1) acc += __uint_as_float(b);
            else if (hi == uT1) atomicAdd(&h_hi[(b >> 8) & 0xffu], 1u);
            g_hist1[hi] = 0u;          // scrub (threshold-independent)
            g_chunk1[b >> 22] = 0u;
        }
    }
    if (t < nc - rs) {
        unsigned int b = __float_as_uint(g_cmp[rs + t]);
        unsigned int hi = b >> 16;
        if (T1 < 0 || hi > uT1) acc += __uint_as_float(b);
        else if (hi == uT1) atomicAdd(&h_hi[(b >> 8) & 0xffu], 1u);
        g_hist1[hi] = 0u;
        g_chunk1[b >> 22] = 0u;
    }
    __syncthreads();
    block_sum_1024(acc, red32, &keep[0]);   // keep[0] = sum above bucket

    unsigned int thr_bits = 0u, rem = 0u;
    if (T1 >= 0) {
        // ---- mid-8 select ----
        suffix_select_256w(h_hi, need1, fnd);
        unsigned int c_hi = fnd[0], k2 = fnd[1];
        unsigned int pre16 = (uT1 << 8) | c_hi;

        // ---- pass 2: low-8 histogram of (T1, c_hi) ----
        for (int j = t; j < nc4; j += TT) {
            uint4 q = cmp4[j];
            unsigned int bb[4] = {q.x, q.y, q.z, q.w};
#pragma unroll
            for (int e = 0; e < 4; e++) {
                if ((bb[e] >> 8) == pre16) atomicAdd(&h_lo[bb[e] & 0xffu], 1u);
            }
        }
        if (t < nc - rs) {
            unsigned int b = __float_as_uint(g_cmp[rs + t]);
            if ((b >> 8) == pre16) atomicAdd(&h_lo[b & 0xffu], 1u);
        }
        __syncthreads();
        suffix_select_256w(h_lo, k2, fnd);
        thr_bits = (pre16 << 8) | fnd[0];
        rem = fnd[1];

        // ---- pass 3: sum bucket-T1 values strictly above threshold ----
        float a2 = 0.f;
        for (int j = t; j < nc4; j += TT) {
            uint4 q = cmp4[j];
            unsigned int bb[4] = {q.x, q.y, q.z, q.w};
#pragma unroll
            for (int e = 0; e < 4; e++) {
                if ((bb[e] >> 16) == uT1 && bb[e] > thr_bits) a2 += __uint_as_float(bb[e]);
            }
        }
        if (t < nc - rs) {
            unsigned int b = __float_as_uint(g_cmp[rs + t]);
            if ((b >> 16) == uT1 && b > thr_bits) a2 += __uint_as_float(b);
        }
        block_sum_1024(a2, red32, &keep[1]);
    } else {
        if (t == 0) keep[1] = 0.f;
        __syncthreads();
    }

    if (t == 0) {
        float neg = keep[0] + keep[1] + (float)rem * __uint_as_float(thr_bits);
        out[0] = (g_pos_sum + neg) / (float)g_npos;
        // reset scalars for next replay (all reads above are done)
        g_pos_sum = 0.f; g_npos = 0u; g_ncand = 0u;
        g_T1 = -1; g_need1 = 0u;
    }
}

extern "C" void kernel_launch(void* const* d_in, const int* in_sizes, int n_in,
                              void* d_out, int out_size) {
    const float* pred = (const float*)d_in[0];
    const float* gts  = (const float*)d_in[1];
    const int*   pos  = (const int*)d_in[2];
    float* out = (float*)d_out;

    compute_kernel<<<CMP_G, CMP_T>>>(pred, gts, pos);
    tail_kernel<<<1, TT>>>(out);
}